// round 1
// baseline (speedup 1.0000x reference)
#include <cuda_runtime.h>
#include <cuda_fp16.h>
#include <cstdint>
#include <cstddef>

// Problem constants
#define NBATCH 4
#define NTOK   2048
#define NCH    1024
#define NHEAD  16
#define NHD    64
#define NROWS  8192   // NBATCH*NTOK

// ---------------- scratch (device globals; no allocs allowed) ----------------
__device__ __half g_xn[(size_t)NROWS * NCH];        // LN output, fp16, row-major [8192][1024]
__device__ __half g_q [(size_t)NROWS * NCH];        // [b][h][t][d]
__device__ __half g_k [(size_t)NROWS * NCH];        // [b][h][t][d]
__device__ __half g_vT[(size_t)NROWS * NCH];        // [b][h][d][t]  (transposed V)
__device__ __half g_y [(size_t)NROWS * NCH];        // attention out, row-major [8192][1024]
__device__ __half g_w16[4][(size_t)NCH * NCH];      // Wq, Wk, Wv, Wo in fp16 [o][c]

// ---------------- PTX helpers ----------------
__device__ __forceinline__ uint32_t smem_u32(const void* p) {
    return (uint32_t)__cvta_generic_to_shared(p);
}
__device__ __forceinline__ void ldm_x4(uint32_t* r, const void* p) {
    uint32_t a = smem_u32(p);
    asm volatile("ldmatrix.sync.aligned.m8n8.x4.shared.b16 {%0,%1,%2,%3}, [%4];"
                 : "=r"(r[0]), "=r"(r[1]), "=r"(r[2]), "=r"(r[3]) : "r"(a));
}
__device__ __forceinline__ void ldm_x2(uint32_t* r, const void* p) {
    uint32_t a = smem_u32(p);
    asm volatile("ldmatrix.sync.aligned.m8n8.x2.shared.b16 {%0,%1}, [%2];"
                 : "=r"(r[0]), "=r"(r[1]) : "r"(a));
}
__device__ __forceinline__ void mma_16816(float* c, const uint32_t* a, const uint32_t* b) {
    asm volatile("mma.sync.aligned.m16n8k16.row.col.f32.f16.f16.f32 "
                 "{%0,%1,%2,%3}, {%4,%5,%6,%7}, {%8,%9}, {%0,%1,%2,%3};"
                 : "+f"(c[0]), "+f"(c[1]), "+f"(c[2]), "+f"(c[3])
                 : "r"(a[0]), "r"(a[1]), "r"(a[2]), "r"(a[3]),
                   "r"(b[0]), "r"(b[1]));
}
__device__ __forceinline__ void cpa16(const void* smem, const void* g) {
    asm volatile("cp.async.cg.shared.global [%0], [%1], 16;"
                 :: "r"(smem_u32(smem)), "l"(g) : "memory");
}
__device__ __forceinline__ void cpa_commit() { asm volatile("cp.async.commit_group;" ::: "memory"); }
__device__ __forceinline__ void cpa_wait0()  { asm volatile("cp.async.wait_group 0;" ::: "memory"); }

__device__ __forceinline__ uint32_t f2h2u(float a, float b) {
    __half2 h = __floats2half2_rn(a, b);   // x = a (low), y = b (high)
    return *reinterpret_cast<uint32_t*>(&h);
}
__device__ __forceinline__ float negInf() { return __int_as_float(0xff800000); }

// ---------------- kernel 1: weight fp32 -> fp16 ----------------
__global__ __launch_bounds__(256) void cvt_kernel(const float* __restrict__ src, int sel) {
    __half* dst = g_w16[sel];
    size_t i = ((size_t)blockIdx.x * blockDim.x + threadIdx.x) * 4;
    if (i < (size_t)NCH * NCH) {
        float4 v = *(const float4*)(src + i);
        __half2* dd = (__half2*)(dst + i);
        dd[0] = __floats2half2_rn(v.x, v.y);
        dd[1] = __floats2half2_rn(v.z, v.w);
    }
}

// ---------------- kernel 2: LayerNorm (fp32 math, fp16 out) ----------------
__global__ __launch_bounds__(256) void ln_kernel(const float* __restrict__ x,
                                                 const float* __restrict__ gamma,
                                                 const float* __restrict__ beta) {
    __shared__ float redS[8], redQ[8];
    const int row = blockIdx.x;
    const int tid = threadIdx.x;
    float4 v = ((const float4*)(x + (size_t)row * NCH))[tid];
    float s = v.x + v.y + v.z + v.w;
    float q = v.x * v.x + v.y * v.y + v.z * v.z + v.w * v.w;
    #pragma unroll
    for (int o = 16; o > 0; o >>= 1) {
        s += __shfl_xor_sync(0xffffffffu, s, o);
        q += __shfl_xor_sync(0xffffffffu, q, o);
    }
    if ((tid & 31) == 0) { redS[tid >> 5] = s; redQ[tid >> 5] = q; }
    __syncthreads();
    float S = 0.f, Q = 0.f;
    #pragma unroll
    for (int i = 0; i < 8; i++) { S += redS[i]; Q += redQ[i]; }
    const float mu = S * (1.0f / NCH);
    const float var = Q * (1.0f / NCH) - mu * mu;
    const float rstd = rsqrtf(var + 1e-5f);
    float4 gv = ((const float4*)gamma)[tid];
    float4 bv = ((const float4*)beta)[tid];
    __half2 h0 = __floats2half2_rn((v.x - mu) * rstd * gv.x + bv.x,
                                   (v.y - mu) * rstd * gv.y + bv.y);
    __half2 h1 = __floats2half2_rn((v.z - mu) * rstd * gv.z + bv.z,
                                   (v.w - mu) * rstd * gv.w + bv.w);
    __half2* dst = (__half2*)(g_xn + (size_t)row * NCH + tid * 4);
    dst[0] = h0; dst[1] = h1;
}

// ---------------- kernel 3: fp16 GEMM  D[M,N] = A[M,K] @ W[N,K]^T ----------------
// mode 0/1/2: A=g_xn, W=Wq/Wk/Wv, write per-head layouts (fp16)
// mode 3:     A=g_y,  W=Wo,       write fp32 to d_out
__device__ __forceinline__ void store_elem(int mode, float* __restrict__ outF,
                                           int r, int c, float v) {
    if (mode == 3) { outF[(size_t)r * NCH + c] = v; return; }
    const int b = r >> 11, t = r & 2047, h = c >> 6, d = c & 63;
    const __half hv = __float2half_rn(v);
    if (mode == 0)      g_q [(((size_t)b * NHEAD + h) * NTOK + t) * NHD + d] = hv;
    else if (mode == 1) g_k [(((size_t)b * NHEAD + h) * NTOK + t) * NHD + d] = hv;
    else                g_vT[(((size_t)b * NHEAD + h) * NHD + d) * NTOK + t] = hv;
}

#define GP 40  // smem pitch in halfs (80B): conflict-free for ldmatrix

__global__ __launch_bounds__(256) void gemm_kernel(float* __restrict__ outF, int mode) {
    const __half* __restrict__ A  = (mode == 3) ? g_y : g_xn;
    const __half* __restrict__ Bw = g_w16[mode];
    __shared__ __half As[2][128 * GP];
    __shared__ __half Bs[2][128 * GP];

    const int tid = threadIdx.x;
    const int lane = tid & 31, warp = tid >> 5;
    const int wm = warp & 1, wn = warp >> 1;          // warp tile 64x32 (2x4 warps)
    const int bM = blockIdx.y * 128, bN = blockIdx.x * 128;

    float acc[4][4][4];
    #pragma unroll
    for (int i = 0; i < 4; i++)
        #pragma unroll
        for (int j = 0; j < 4; j++)
            #pragma unroll
            for (int e = 0; e < 4; e++) acc[i][j][e] = 0.f;

    const int lr  = tid >> 2;          // 0..63
    const int lch = (tid & 3) * 8;     // half offset of 16B chunk

    // prologue: tile 0
    {
        const __half* a0 = A  + (size_t)(bM + lr) * NCH + lch;
        const __half* b0 = Bw + (size_t)(bN + lr) * NCH + lch;
        cpa16(&As[0][lr * GP + lch],        a0);
        cpa16(&As[0][(lr + 64) * GP + lch], a0 + (size_t)64 * NCH);
        cpa16(&Bs[0][lr * GP + lch],        b0);
        cpa16(&Bs[0][(lr + 64) * GP + lch], b0 + (size_t)64 * NCH);
        cpa_commit();
    }

    const int KT = NCH / 32;   // 32
    for (int kt = 0; kt < KT; kt++) {
        cpa_wait0();
        __syncthreads();
        if (kt + 1 < KT) {
            const int k0 = (kt + 1) * 32;
            const int buf = (kt + 1) & 1;
            const __half* a0 = A  + (size_t)(bM + lr) * NCH + k0 + lch;
            const __half* b0 = Bw + (size_t)(bN + lr) * NCH + k0 + lch;
            cpa16(&As[buf][lr * GP + lch],        a0);
            cpa16(&As[buf][(lr + 64) * GP + lch], a0 + (size_t)64 * NCH);
            cpa16(&Bs[buf][lr * GP + lch],        b0);
            cpa16(&Bs[buf][(lr + 64) * GP + lch], b0 + (size_t)64 * NCH);
            cpa_commit();
        }
        const int buf = kt & 1;
        #pragma unroll
        for (int kk = 0; kk < 32; kk += 16) {
            uint32_t af[4][4];
            const int rA = wm * 64 + (lane & 15);
            const int cA = kk + 8 * (lane >> 4);
            #pragma unroll
            for (int mt = 0; mt < 4; mt++)
                ldm_x4(af[mt], &As[buf][(rA + mt * 16) * GP + cA]);
            uint32_t bf[4][2];
            const int rB = wn * 32 + (lane & 7);
            const int cB = kk + 8 * ((lane >> 3) & 1);
            #pragma unroll
            for (int nt = 0; nt < 4; nt++)
                ldm_x2(bf[nt], &Bs[buf][(rB + nt * 8) * GP + cB]);
            #pragma unroll
            for (int mt = 0; mt < 4; mt++)
                #pragma unroll
                for (int nt = 0; nt < 4; nt++)
                    mma_16816(acc[mt][nt], af[mt], bf[nt]);
        }
    }

    // epilogue
    #pragma unroll
    for (int mt = 0; mt < 4; mt++) {
        #pragma unroll
        for (int nt = 0; nt < 4; nt++) {
            const int r0 = bM + wm * 64 + mt * 16 + (lane >> 2);
            const int c0 = bN + wn * 32 + nt * 8 + (lane & 3) * 2;
            const float* v = acc[mt][nt];
            store_elem(mode, outF, r0,     c0,     v[0]);
            store_elem(mode, outF, r0,     c0 + 1, v[1]);
            store_elem(mode, outF, r0 + 8, c0,     v[2]);
            store_elem(mode, outF, r0 + 8, c0 + 1, v[3]);
        }
    }
}

// ---------------- kernel 4: flash attention (causal), fp16 MMA, fp32 softmax --------
#define AP 72   // smem pitch (144B) for 64-wide fp16 tiles, conflict-free ldmatrix

__global__ __launch_bounds__(128) void attn_kernel() {
    const int qt = blockIdx.x;           // 0..31
    const int bh = blockIdx.y;           // 0..63
    const int tid = threadIdx.x;
    const int lane = tid & 31, warp = tid >> 5;
    const int q0 = qt * 64;

    const __half* __restrict__ Qg = g_q  + (size_t)bh * NTOK * NHD;
    const __half* __restrict__ Kg = g_k  + (size_t)bh * NTOK * NHD;
    const __half* __restrict__ Vg = g_vT + (size_t)bh * NHD * NTOK;

    __shared__ __half Qs[64 * AP];
    __shared__ __half Ks[64 * AP];
    __shared__ __half Vs[64 * AP];

    // load Q tile (64x64): 512 16B chunks, 4 per thread
    #pragma unroll
    for (int i = 0; i < 4; i++) {
        const int idx = tid + i * 128;
        const int r = idx >> 3, ch = (idx & 7) * 8;
        *(uint4*)&Qs[r * AP + ch] = *(const uint4*)(Qg + (size_t)(q0 + r) * NHD + ch);
    }
    __syncthreads();

    // Q fragments (scaled by 1/8 = head_dim^-0.5, exact in fp16)
    uint32_t qf[4][4];
    {
        const int rA = warp * 16 + (lane & 15);
        const int cA = 8 * (lane >> 4);
        #pragma unroll
        for (int kc = 0; kc < 4; kc++)
            ldm_x4(qf[kc], &Qs[rA * AP + kc * 16 + cA]);
        const __half2 sc = __float2half2_rn(0.125f);
        #pragma unroll
        for (int kc = 0; kc < 4; kc++)
            #pragma unroll
            for (int e = 0; e < 4; e++) {
                __half2 h = *reinterpret_cast<__half2*>(&qf[kc][e]);
                h = __hmul2(h, sc);
                qf[kc][e] = *reinterpret_cast<uint32_t*>(&h);
            }
    }

    float m0 = negInf(), m1 = negInf();
    float l0 = 0.f, l1 = 0.f;
    float o[8][4];
    #pragma unroll
    for (int nt = 0; nt < 8; nt++)
        #pragma unroll
        for (int e = 0; e < 4; e++) o[nt][e] = 0.f;

    const int rB = lane & 7;
    const int cB = 8 * ((lane >> 3) & 1);

    for (int j = 0; j <= qt; j++) {
        __syncthreads();   // previous iteration's MMA reads done before overwrite
        #pragma unroll
        for (int i = 0; i < 4; i++) {
            const int idx = tid + i * 128;
            const int r = idx >> 3, ch = (idx & 7) * 8;
            *(uint4*)&Ks[r * AP + ch] = *(const uint4*)(Kg + (size_t)(j * 64 + r) * NHD + ch);
            *(uint4*)&Vs[r * AP + ch] = *(const uint4*)(Vg + (size_t)r * NTOK + j * 64 + ch);
        }
        __syncthreads();

        // S = (Q*scale) @ K^T : 16x64 per warp
        float s[8][4];
        #pragma unroll
        for (int nt = 0; nt < 8; nt++)
            #pragma unroll
            for (int e = 0; e < 4; e++) s[nt][e] = 0.f;
        #pragma unroll
        for (int kc = 0; kc < 4; kc++) {
            #pragma unroll
            for (int nt = 0; nt < 8; nt++) {
                uint32_t kf[2];
                ldm_x2(kf, &Ks[(nt * 8 + rB) * AP + kc * 16 + cB]);
                mma_16816(s[nt], qf[kc], kf);
            }
        }

        // causal mask on the diagonal tile
        if (j == qt) {
            const int rl = warp * 16 + (lane >> 2);
            const int cb = (lane & 3) * 2;
            #pragma unroll
            for (int nt = 0; nt < 8; nt++) {
                const int c0 = nt * 8 + cb;
                if (c0     > rl)     s[nt][0] = -1e30f;
                if (c0 + 1 > rl)     s[nt][1] = -1e30f;
                if (c0     > rl + 8) s[nt][2] = -1e30f;
                if (c0 + 1 > rl + 8) s[nt][3] = -1e30f;
            }
        }

        // online softmax (rows r and r+8 per lane-group)
        float mx0 = -3.0e38f, mx1 = -3.0e38f;
        #pragma unroll
        for (int nt = 0; nt < 8; nt++) {
            mx0 = fmaxf(mx0, fmaxf(s[nt][0], s[nt][1]));
            mx1 = fmaxf(mx1, fmaxf(s[nt][2], s[nt][3]));
        }
        mx0 = fmaxf(mx0, __shfl_xor_sync(0xffffffffu, mx0, 1));
        mx0 = fmaxf(mx0, __shfl_xor_sync(0xffffffffu, mx0, 2));
        mx1 = fmaxf(mx1, __shfl_xor_sync(0xffffffffu, mx1, 1));
        mx1 = fmaxf(mx1, __shfl_xor_sync(0xffffffffu, mx1, 2));
        const float mn0 = fmaxf(m0, mx0), mn1 = fmaxf(m1, mx1);
        const float cor0 = __expf(m0 - mn0), cor1 = __expf(m1 - mn1);
        m0 = mn0; m1 = mn1;
        float sum0 = 0.f, sum1 = 0.f;
        #pragma unroll
        for (int nt = 0; nt < 8; nt++) {
            s[nt][0] = __expf(s[nt][0] - mn0); sum0 += s[nt][0];
            s[nt][1] = __expf(s[nt][1] - mn0); sum0 += s[nt][1];
            s[nt][2] = __expf(s[nt][2] - mn1); sum1 += s[nt][2];
            s[nt][3] = __expf(s[nt][3] - mn1); sum1 += s[nt][3];
        }
        sum0 += __shfl_xor_sync(0xffffffffu, sum0, 1);
        sum0 += __shfl_xor_sync(0xffffffffu, sum0, 2);
        sum1 += __shfl_xor_sync(0xffffffffu, sum1, 1);
        sum1 += __shfl_xor_sync(0xffffffffu, sum1, 2);
        l0 = l0 * cor0 + sum0;
        l1 = l1 * cor1 + sum1;
        #pragma unroll
        for (int nt = 0; nt < 8; nt++) {
            o[nt][0] *= cor0; o[nt][1] *= cor0;
            o[nt][2] *= cor1; o[nt][3] *= cor1;
        }

        // P fragments directly from S accumulators (no smem round-trip)
        uint32_t pf[4][4];
        #pragma unroll
        for (int kc = 0; kc < 4; kc++) {
            pf[kc][0] = f2h2u(s[2 * kc][0],     s[2 * kc][1]);
            pf[kc][1] = f2h2u(s[2 * kc][2],     s[2 * kc][3]);
            pf[kc][2] = f2h2u(s[2 * kc + 1][0], s[2 * kc + 1][1]);
            pf[kc][3] = f2h2u(s[2 * kc + 1][2], s[2 * kc + 1][3]);
        }

        // O += P @ V  (V^T tiles in Vs: rows = d, cols = key)
        #pragma unroll
        for (int kc = 0; kc < 4; kc++) {
            #pragma unroll
            for (int nt = 0; nt < 8; nt++) {
                uint32_t vf[2];
                ldm_x2(vf, &Vs[(nt * 8 + rB) * AP + kc * 16 + cB]);
                mma_16816(o[nt], pf[kc], vf);
            }
        }
    }

    // finalize: divide by row sums, store to g_y row-major [b*T+t][h*64+d]
    const int b = bh >> 4, h = bh & 15;
    const int trow = q0 + warp * 16 + (lane >> 2);
    const float inv0 = 1.0f / l0, inv1 = 1.0f / l1;
    #pragma unroll
    for (int nt = 0; nt < 8; nt++) {
        const int col = h * 64 + nt * 8 + (lane & 3) * 2;
        const size_t base = (size_t)(b * NTOK + trow) * NCH + col;
        *(__half2*)(g_y + base) = __floats2half2_rn(o[nt][0] * inv0, o[nt][1] * inv0);
        *(__half2*)(g_y + base + (size_t)8 * NCH) =
            __floats2half2_rn(o[nt][2] * inv1, o[nt][3] * inv1);
    }
}

// ---------------- launch ----------------
extern "C" void kernel_launch(void* const* d_in, const int* in_sizes, int n_in,
                              void* d_out, int out_size) {
    (void)in_sizes; (void)n_in; (void)out_size;
    const float* x     = (const float*)d_in[0];
    const float* gamma = (const float*)d_in[1];
    const float* beta  = (const float*)d_in[2];

    for (int w = 0; w < 4; w++)
        cvt_kernel<<<1024, 256>>>((const float*)d_in[3 + w], w);

    ln_kernel<<<NROWS, 256>>>(x, gamma, beta);

    dim3 gg(NCH / 128, NROWS / 128);   // (8, 64)
    gemm_kernel<<<gg, 256>>>(nullptr, 0);   // Q
    gemm_kernel<<<gg, 256>>>(nullptr, 1);   // K
    gemm_kernel<<<gg, 256>>>(nullptr, 2);   // V (transposed store)

    attn_kernel<<<dim3(NTOK / 64, NBATCH * NHEAD), 128>>>();

    gemm_kernel<<<gg, 256>>>((float*)d_out, 3);  // output projection -> fp32
}